// round 11
// baseline (speedup 1.0000x reference)
#include <cuda_runtime.h>

#define B_ROWS 16384
#define IN_DIM 2048
#define E_NUM 16
#define KMAX 8

#define TEMP_F 0.7f
#define P_MIN_F 0.92f
#define CLOSE_F 0.82f   // P_MIN - CLOSE_DELTA

#define SC_OFF (B_ROWS * KMAX)          // 131072
#define MK_OFF (2 * B_ROWS * KMAX)      // 262144
#define KV_OFF (3 * B_ROWS * KMAX)      // 393216

#define THREADS 512
#define ROWS_PER_WARP 8
#define ROWS_PER_BLOCK 128              // 16 warps * 8 rows
#define NCHUNK 32                       // x chunks of 64 K-floats
#define CHUNK_FLOATS 64
#define W1_BYTES (E_NUM * IN_DIM * 4)   // 131072
#define XBUF_BYTES (ROWS_PER_BLOCK * CHUNK_FLOATS * 4)  // 32768
#define SMEM_TOTAL (W1_BYTES + 3 * XBUF_BYTES)          // 229376

typedef unsigned long long u64;

// Packed 2xfp32 FMA (SASS FFMA2) — only reachable via PTX fma.rn.f32x2.
__device__ __forceinline__ u64 ffma2(u64 a, u64 b, u64 c) {
    u64 d;
    asm("fma.rn.f32x2 %0, %1, %2, %3;" : "=l"(d) : "l"(a), "l"(b), "l"(c));
    return d;
}

__device__ __forceinline__ void cp_async16(unsigned saddr, const void* gaddr) {
    asm volatile("cp.async.cg.shared.global [%0], [%1], 16;" :: "r"(saddr), "l"(gaddr));
}
__device__ __forceinline__ void cp_commit() {
    asm volatile("cp.async.commit_group;");
}
__device__ __forceinline__ void cp_wait1() {
    asm volatile("cp.async.wait_group 1;");
}

// stage one 64-float x chunk for all 128 block rows: 2048 granules / 512 thr
__device__ __forceinline__ void stage_x(unsigned dst_sb, const float* xg,
                                        int c, int tid) {
#pragma unroll
    for (int i = 0; i < 4; i++) {
        int idx = tid + i * THREADS;            // 0..2047
        int row = idx >> 4, kq = idx & 15;
        cp_async16(dst_sb + idx * 16,
                   xg + (size_t)row * IN_DIM + c * CHUNK_FLOATS + kq * 4);
    }
}

__global__ __launch_bounds__(THREADS, 1) void dyn_top_gate_kernel(
    const float* __restrict__ x,
    const float* __restrict__ W1,
    const float* __restrict__ W2,
    float* __restrict__ out)
{
    extern __shared__ __align__(16) char smem[];
    char* xs0 = smem + W1_BYTES;

    const int tid = threadIdx.x;
    const int lane = tid & 31;
    const int wid = tid >> 5;                    // 0..15
    const int q = (lane >> 3) & 3;               // expert quarter
    const int s = lane & 7;                      // K sub-slice
    const int row0 = blockIdx.x * ROWS_PER_BLOCK + wid * ROWS_PER_WARP;

    const float* xg = x + (size_t)blockIdx.x * ROWS_PER_BLOCK * IN_DIM;

    // ---- stage all of W1, re-laid-out: granule((t*16+e)*8+s) = W1[e][t*32+s*4]
    {
        unsigned sb = (unsigned)__cvta_generic_to_shared(smem);
#pragma unroll
        for (int i = 0; i < 16; i++) {
            int idx = tid + i * THREADS;         // 0..8191
            int ss = idx & 7, e = (idx >> 3) & 15, t = idx >> 7;
            cp_async16(sb + idx * 16, W1 + e * IN_DIM + t * 32 + ss * 4);
        }
        cp_commit();
    }
    // ---- prologue: stage x chunks 0 and 1
    unsigned xsb0 = (unsigned)__cvta_generic_to_shared(xs0);
    stage_x(xsb0, xg, 0, tid);
    cp_commit();
    stage_x(xsb0 + XBUF_BYTES, xg, 1, tid);
    cp_commit();

    u64 acc[32];                                 // acc[eq*8 + r], f32x2 each
#pragma unroll
    for (int i = 0; i < 32; i++) acc[i] = 0ull;

    // lane-fixed smem sub-pointers
    const char* wq = smem + q * 512 + s * 16;    // + t*2048 + eq*128
    const int xroff = wid * ROWS_PER_WARP * 256 + s * 16;

    int cb = 0;                                  // c % 3
#pragma unroll 1
    for (int c = 0; c < NCHUNK; c++) {
        cp_wait1();                              // chunk c staged (group c done)
        __syncthreads();                         // visible to all; ring slot free
        if (c + 2 < NCHUNK) {
            int sbuf = cb + 2; if (sbuf >= 3) sbuf -= 3;   // (c+2)%3
            stage_x(xsb0 + sbuf * XBUF_BYTES, xg, c + 2, tid);
        }
        cp_commit();

        const char* xr = xs0 + cb * XBUF_BYTES + xroff;

#pragma unroll
        for (int b = 0; b < 2; b++) {            // 2 bodies of 32 K-floats
            const int t = 2 * c + b;
            ulonglong2 xv[ROWS_PER_WARP];
#pragma unroll
            for (int r = 0; r < ROWS_PER_WARP; r++)
                xv[r] = *reinterpret_cast<const ulonglong2*>(xr + r * 256 + b * 128);
#pragma unroll
            for (int eq = 0; eq < 4; eq++) {
                ulonglong2 w = *reinterpret_cast<const ulonglong2*>(
                    wq + (size_t)t * 2048 + eq * 128);
#pragma unroll
                for (int r = 0; r < ROWS_PER_WARP; r++) {
                    acc[eq * 8 + r] = ffma2(w.x, xv[r].x, acc[eq * 8 + r]);
                    acc[eq * 8 + r] = ffma2(w.y, xv[r].y, acc[eq * 8 + r]);
                }
            }
        }
        cb++; if (cb == 3) cb = 0;
    }

    // ---- collapse f32x2 pairs, butterfly over s (xor 4,2,1) ----------------
    // vals[v], v = eq*8 + r. Lane (q,s) ends holding full sums for
    // v in {4s..4s+3}: e = 4q + (v>>3), r = v&7.
    float vals[32];
#pragma unroll
    for (int i = 0; i < 32; i++) {
        float2 p = *reinterpret_cast<float2*>(&acc[i]);
        vals[i] = p.x + p.y;
    }
#pragma unroll
    for (int off = 4, cnt = 32; off >= 1; off >>= 1, cnt >>= 1) {
        const bool up = (lane & off) != 0;
#pragma unroll
        for (int i = 0; i < cnt / 2; i++) {
            float send = up ? vals[i] : vals[i + cnt / 2];
            float keep = up ? vals[i + cnt / 2] : vals[i];
            float recv = __shfl_xor_sync(0xffffffffu, send, off);
            vals[i] = keep + recv;
        }
    }

    float th[4];
#pragma unroll
    for (int j = 0; j < 4; j++) th[j] = tanhf(vals[j]);

    // ---- epilogue: lane = f + 16*gseg handles expert f, rows 4*gseg+rr -----
    const int gseg = lane >> 4;
    const int f = lane & 15;

    float w2f[E_NUM];
#pragma unroll
    for (int e = 0; e < E_NUM; e++) w2f[e] = __ldg(W2 + f * E_NUM + e);

#pragma unroll
    for (int rr = 0; rr < 4; rr++) {
        const int row = row0 + 4 * gseg + rr;

        // h[e] for this row lives at lane 8*(e>>2)+2*(e&3)+gseg, element rr
        float logit = 0.f;
#pragma unroll
        for (int e = 0; e < E_NUM; e++) {
            int srcl = 8 * (e >> 2) + 2 * (e & 3) + gseg;
            float hv = __shfl_sync(0xffffffffu, th[rr], srcl);
            logit = fmaf(hv, w2f[e], logit);
        }
        logit = logit / TEMP_F;

        // softmax over the 16-lane segment
        float m = logit;
#pragma unroll
        for (int sh = 8; sh > 0; sh >>= 1)
            m = fmaxf(m, __shfl_xor_sync(0xffffffffu, m, sh, 16));

        float ex = expf(logit - m);
        float sum = ex;
#pragma unroll
        for (int sh = 8; sh > 0; sh >>= 1)
            sum += __shfl_xor_sync(0xffffffffu, sum, sh, 16);
        float prob = ex / sum;

        // stable descending rank (ties -> smaller expert index first)
        int rank = 0;
#pragma unroll
        for (int g2 = 0; g2 < E_NUM; g2++) {
            float lv = __shfl_sync(0xffffffffu, logit, g2, 16);
            rank += (lv > logit) || (lv == logit && g2 < f);
        }

        // inclusive cumulative prob at my rank; pick p1,p2,p3
        float cum = 0.f, p1 = 0.f, p2 = 0.f, p3 = 0.f;
#pragma unroll
        for (int g2 = 0; g2 < E_NUM; g2++) {
            float pv = __shfl_sync(0xffffffffu, prob, g2, 16);
            int rv = __shfl_sync(0xffffffffu, rank, g2, 16);
            if (rv <= rank) cum += pv;
            if (rv == 0) p1 = pv;
            if (rv == 1) p2 = pv;
            if (rv == 2) p3 = pv;
        }

        // idx_first = #ranks with cum < P_MIN (cum monotone in rank)
        int cnt2 = 0;
#pragma unroll
        for (int g2 = 0; g2 < E_NUM; g2++) {
            float cv = __shfl_sync(0xffffffffu, cum, g2, 16);
            cnt2 += (cv < P_MIN_F);
        }
        if (cnt2 > E_NUM - 1) cnt2 = E_NUM - 1;
        int kv = cnt2 + 1;

        float gap12 = p1 - p2;
        float gap23 = p2 - p3;
        if (p1 >= 0.46f && gap12 >= 0.1f) kv = 1;
        float cum1 = p1 + p2;
        if (kv > 2 && (cum1 >= CLOSE_F || p3 <= 0.12f || gap23 <= 0.03f)) kv = 2;
        kv = max(1, min(3, kv));

        // ----- writes -----
        if (rank < KMAX) {
            int o = row * KMAX + rank;
            out[o] = (float)f;                                   // top_indices
            out[SC_OFF + o] = (rank < kv) ? prob : 0.f;          // top_scores
            out[MK_OFF + o] = (rank < kv) ? 1.f : 0.f;           // top_mask
        }
        if (rank == 0) out[KV_OFF + row] = (float)kv;            // k_vec
    }
}

extern "C" void kernel_launch(void* const* d_in, const int* in_sizes, int n_in,
                              void* d_out, int out_size) {
    const float* x  = (const float*)d_in[0];
    const float* W1 = (const float*)d_in[1];
    const float* W2 = (const float*)d_in[2];
    float* out = (float*)d_out;

    static int attr_set = 0;
    if (!attr_set) {
        cudaFuncSetAttribute(dyn_top_gate_kernel,
                             cudaFuncAttributeMaxDynamicSharedMemorySize,
                             SMEM_TOTAL);
        attr_set = 1;
    }

    const int blocks = B_ROWS / ROWS_PER_BLOCK;   // 128 — single wave on 148 SMs
    dyn_top_gate_kernel<<<blocks, THREADS, SMEM_TOTAL>>>(x, W1, W2, out);
}